// round 9
// baseline (speedup 1.0000x reference)
#include <cuda_runtime.h>
#include <cuda_bf16.h>
#include <cstdint>
#include <cstddef>

#define LL   6
#define TT   256
#define NNH  128
#define DDIM 512
#define HH   8
#define DHH  64
#define DFF  2048
#define SSL  512
#define PSD  (NNH * DDIM)      // 65536, one partial slab (N x D)

typedef unsigned long long u64x2;

__device__ __forceinline__ u64x2 pk2(float a, float b) {
    u64x2 r; asm("mov.b64 %0, {%1, %2};" : "=l"(r) : "f"(a), "f"(b)); return r;
}
__device__ __forceinline__ float2 upk(u64x2 v) {
    float2 r; asm("mov.b64 {%0, %1}, %2;" : "=f"(r.x), "=f"(r.y) : "l"(v)); return r;
}
__device__ __forceinline__ u64x2 ffma2(u64x2 a, u64x2 b, u64x2 c) {
    u64x2 d; asm("fma.rn.f32x2 %0, %1, %2, %3;" : "=l"(d) : "l"(a), "l"(b), "l"(c)); return d;
}

// scratch (__device__ globals; no allocation allowed)
__device__ float  g_tgt  [NNH * DDIM];
__device__ float  g_qt   [NNH * HH * DDIM];
__device__ float  g_partA[8 * NNH * DDIM];     // also 2 slabs of N*DFF
__device__ float  g_partB[8 * NNH * DDIM];
__device__ float  g_facc [NNH * 4 * HH * DDIM];
__device__ float2 g_fst  [NNH * 4 * HH];

// ---------------- embedding + positional encoding ----------------
__global__ __launch_bounds__(128) void embed_kernel(
    const int* __restrict__ toks, const float* __restrict__ embd,
    const int* __restrict__ offp, float* __restrict__ out)
{
    int n = blockIdx.x, tid = threadIdx.x;
    const float* erow = embd + (size_t)toks[n] * DDIM;
    float off = (float)offp[0];
    const float c = -9.210340371976184f / (float)DDIM;
    float4 v;
#pragma unroll
    for (int j = 0; j < 4; j++) {
        int d = tid * 4 + j;
        float ang = off * expf((float)(d & ~1) * c);
        ((float*)&v)[j] = erow[d] + ((d & 1) ? cosf(ang) : sinf(ang));
    }
    *(float4*)(out + (size_t)n * DDIM + tid * 4) = v;
}

// ---------------- GEMM v3 ----------------
// C[n,m] = sum_k Aeff[n,k]*W[m,k]  (WT: W[k,m]); 32x64 tile, 256 thr, KC=32.
// AM=0: Aeff = A.
// AM=1: Aeff = relu?(ascale*(sum_{s<ks2} A[s*aSeg + ...] + abias[..])).
// AM=2: Aeff = sum_{s<4} co_s(n,h) * A[s*aSeg + ...]   (softmax seg merge).
struct GP {
    const float* A; int lda; int aOffZ; long aSeg; int ks2;
    const float* abias; int abOff; float ascale; int arelu;
    const float2* fst;
    const float* W; int ldw; int wOffZ;
    float* C; int ldc; int cOffZ; long cSeg;
    int K; int KS;
};

template<int AM, bool WT>
__global__ __launch_bounds__(256) void gemm3(GP p)
{
    __shared__ __align__(16) float As[2][32][34];
    __shared__ __align__(16) float Ws[2][32][68];
    int z = blockIdx.z, h = z / p.KS, ks = z - h * p.KS;
    long koff = (long)ks * p.K;
    const float* A = p.A + (size_t)h * p.aOffZ + koff;
    const float* W = p.W + (size_t)h * p.wOffZ + (WT ? (size_t)koff * p.ldw : (size_t)koff);
    float* C = p.C + (size_t)h * p.cOffZ + (size_t)ks * p.cSeg;
    int n0 = blockIdx.x * 32, m0 = blockIdx.y * 64;
    int t = threadIdx.x, tx = t & 15, ty = t >> 4;
    int ar = t >> 3, ak = (t & 7) * 4;
    int wr = t >> 2, wk = (t & 3) * 8;
    int wtk = t >> 4, wtm = (t & 15) * 4;

    const float* abp = nullptr;
    if (AM == 1) abp = p.abias + (size_t)h * p.abOff + koff;

    float co[4] = {0.f, 0.f, 0.f, 0.f};
    if (AM == 2) {
        const float2* fp = p.fst + h;
        int n = n0 + ar;
        float2 s0 = fp[n*32], s1 = fp[n*32+8], s2 = fp[n*32+16], s3 = fp[n*32+24];
        float Mg = fmaxf(fmaxf(s0.x, s1.x), fmaxf(s2.x, s3.x));
        float e0 = __expf(s0.x - Mg), e1 = __expf(s1.x - Mg);
        float e2 = __expf(s2.x - Mg), e3 = __expf(s3.x - Mg);
        float inv = 1.f / (s0.y*e0 + s1.y*e1 + s2.y*e2 + s3.y*e3);
        co[0] = e0*inv; co[1] = e1*inv; co[2] = e2*inv; co[3] = e3*inv;
    }

    auto loadA = [&](int kc) -> float4 {
        if (AM == 0) {
            return *(const float4*)&A[(size_t)(n0 + ar) * p.lda + kc + ak];
        } else if (AM == 1) {
            float4 v = *(const float4*)&abp[kc + ak];
            for (int s = 0; s < p.ks2; s++) {
                float4 pv = *(const float4*)&A[(size_t)s * p.aSeg + (size_t)(n0 + ar) * p.lda + kc + ak];
                v.x += pv.x; v.y += pv.y; v.z += pv.z; v.w += pv.w;
            }
            v.x *= p.ascale; v.y *= p.ascale; v.z *= p.ascale; v.w *= p.ascale;
            if (p.arelu) {
                v.x = fmaxf(v.x, 0.f); v.y = fmaxf(v.y, 0.f);
                v.z = fmaxf(v.z, 0.f); v.w = fmaxf(v.w, 0.f);
            }
            return v;
        } else {
            const float* base = A + (size_t)(n0 + ar) * p.lda + kc + ak;
            float4 v = make_float4(0.f, 0.f, 0.f, 0.f);
#pragma unroll
            for (int s = 0; s < 4; s++) {
                float4 pv = *(const float4*)&base[(size_t)s * p.aSeg];
                v.x += co[s]*pv.x; v.y += co[s]*pv.y;
                v.z += co[s]*pv.z; v.w += co[s]*pv.w;
            }
            return v;
        }
    };
    auto loadW = [&](int kc, float4& w0, float4& w1) {
        if (WT) {
            w0 = *(const float4*)&W[(size_t)(kc + wtk)      * p.ldw + m0 + wtm];
            w1 = *(const float4*)&W[(size_t)(kc + wtk + 16) * p.ldw + m0 + wtm];
        } else {
            w0 = *(const float4*)&W[(size_t)(m0 + wr) * p.ldw + kc + wk];
            w1 = *(const float4*)&W[(size_t)(m0 + wr) * p.ldw + kc + wk + 4];
        }
    };

    u64x2 acc[2][2];
    acc[0][0] = acc[0][1] = acc[1][0] = acc[1][1] = pk2(0.f, 0.f);

    float4 ra = loadA(0);
    float4 rw0, rw1; loadW(0, rw0, rw1);
    int buf = 0;
    for (int kc = 0; kc < p.K; kc += 32) {
        As[buf][ak+0][ar] = ra.x; As[buf][ak+1][ar] = ra.y;
        As[buf][ak+2][ar] = ra.z; As[buf][ak+3][ar] = ra.w;
        if (WT) {
            *(float4*)&Ws[buf][wtk][wtm]      = rw0;
            *(float4*)&Ws[buf][wtk + 16][wtm] = rw1;
        } else {
            Ws[buf][wk+0][wr] = rw0.x; Ws[buf][wk+1][wr] = rw0.y;
            Ws[buf][wk+2][wr] = rw0.z; Ws[buf][wk+3][wr] = rw0.w;
            Ws[buf][wk+4][wr] = rw1.x; Ws[buf][wk+5][wr] = rw1.y;
            Ws[buf][wk+6][wr] = rw1.z; Ws[buf][wk+7][wr] = rw1.w;
        }
        __syncthreads();
        if (kc + 32 < p.K) { ra = loadA(kc + 32); loadW(kc + 32, rw0, rw1); }
#pragma unroll
        for (int kk = 0; kk < 32; kk++) {
            float2 av = *(const float2*)&As[buf][kk][ty * 2];
            u64x2 w0 = *(const u64x2*)&Ws[buf][kk][tx * 4];
            u64x2 w1 = *(const u64x2*)&Ws[buf][kk][tx * 4 + 2];
            u64x2 a0 = pk2(av.x, av.x), a1 = pk2(av.y, av.y);
            acc[0][0] = ffma2(a0, w0, acc[0][0]);
            acc[0][1] = ffma2(a0, w1, acc[0][1]);
            acc[1][0] = ffma2(a1, w0, acc[1][0]);
            acc[1][1] = ffma2(a1, w1, acc[1][1]);
        }
        buf ^= 1;
    }

    int mc = m0 + tx * 4;
#pragma unroll
    for (int i = 0; i < 2; i++) {
        int row = n0 + ty * 2 + i;
        float2 f0 = upk(acc[i][0]), f1 = upk(acc[i][1]);
        float4 v = {f0.x, f0.y, f1.x, f1.y};
        *(float4*)&C[(size_t)row * p.ldc + mc] = v;
    }
}

// ---- fused split-K reduce + bias + residual + layernorm (block per row) ----
__global__ __launch_bounds__(128) void ln_red_kernel(
    const float* __restrict__ part, long PS, int KS,
    const float* __restrict__ bias, const float* __restrict__ res,
    const float* __restrict__ w, const float* __restrict__ b,
    float* __restrict__ out)
{
    int n = blockIdx.x, t = threadIdx.x, warp = t >> 5, lane = t & 31;
    size_t idx = (size_t)n * DDIM + t * 4;
    float4 xv = make_float4(0.f, 0.f, 0.f, 0.f);
    for (int ks = 0; ks < KS; ks++) {
        float4 p = *(const float4*)(part + (size_t)ks * PS + idx);
        xv.x += p.x; xv.y += p.y; xv.z += p.z; xv.w += p.w;
    }
    float4 bb = *(const float4*)(bias + t * 4);
    float4 rr = *(const float4*)(res + idx);
    xv.x += bb.x + rr.x; xv.y += bb.y + rr.y;
    xv.z += bb.z + rr.z; xv.w += bb.w + rr.w;

    float s  = xv.x + xv.y + xv.z + xv.w;
    float sq = xv.x*xv.x + xv.y*xv.y + xv.z*xv.z + xv.w*xv.w;
#pragma unroll
    for (int off = 16; off > 0; off >>= 1) {
        s  += __shfl_xor_sync(0xffffffffu, s,  off);
        sq += __shfl_xor_sync(0xffffffffu, sq, off);
    }
    __shared__ float2 rb[4];
    if (lane == 0) rb[warp] = make_float2(s, sq);
    __syncthreads();
    float S = 0.f, Q = 0.f;
#pragma unroll
    for (int i = 0; i < 4; i++) { S += rb[i].x; Q += rb[i].y; }
    float mean = S * (1.0f / DDIM);
    float var  = Q * (1.0f / DDIM) - mean * mean;
    float r = rsqrtf(var + 1e-5f);
    float4 wv = *(const float4*)(w + t * 4);
    float4 bv = *(const float4*)(b + t * 4);
    float4 o;
    o.x = (xv.x - mean) * r * wv.x + bv.x;
    o.y = (xv.y - mean) * r * wv.y + bv.y;
    o.z = (xv.z - mean) * r * wv.z + bv.z;
    o.w = (xv.w - mean) * r * wv.w + bv.w;
    *(float4*)(out + idx) = o;
}

// ---------------- flash attention (folded projections) ----------------
__device__ __forceinline__ void f_load(u64x2* dst, const float* kvn,
    const float4* erow, int t, int Tmain, long rs, int lane)
{
    const float4* rp = (t < Tmain) ? (const float4*)(kvn + (size_t)t * rs) : erow;
#pragma unroll
    for (int qi = 0; qi < 4; qi++) {
        float4 v = __ldg(&rp[lane + 32 * qi]);
        dst[2*qi] = pk2(v.x, v.y); dst[2*qi+1] = pk2(v.z, v.w);
    }
}
__device__ __forceinline__ void f_step(const u64x2* kvp, const u64x2 qtr[2][8],
    const float qb[2], float nm, float mh[2], float sh[2], u64x2 acc[2][8])
{
    float sc[2];
#pragma unroll
    for (int hh = 0; hh < 2; hh++) {
        u64x2 d0 = pk2(0.f, 0.f), d1 = pk2(0.f, 0.f);
#pragma unroll
        for (int qi = 0; qi < 4; qi++) {
            d0 = ffma2(qtr[hh][2*qi],   kvp[2*qi],   d0);
            d1 = ffma2(qtr[hh][2*qi+1], kvp[2*qi+1], d1);
        }
        float2 f0 = upk(d0), f1 = upk(d1);
        sc[hh] = f0.x + f0.y + f1.x + f1.y;
    }
#pragma unroll
    for (int off = 16; off > 0; off >>= 1) {
        sc[0] += __shfl_xor_sync(0xffffffffu, sc[0], off);
        sc[1] += __shfl_xor_sync(0xffffffffu, sc[1], off);
    }
#pragma unroll
    for (int hh = 0; hh < 2; hh++) {
        float s = sc[hh] + qb[hh] + nm;
        if (s <= mh[hh]) {
            float p = __expf(s - mh[hh]);
            sh[hh] += p;
            u64x2 p2 = pk2(p, p);
#pragma unroll
            for (int qi = 0; qi < 8; qi++)
                acc[hh][qi] = ffma2(kvp[qi], p2, acc[hh][qi]);
        } else {
            float c0 = __expf(mh[hh] - s);
            sh[hh] = sh[hh] * c0 + 1.f;
            mh[hh] = s;
            u64x2 c2 = pk2(c0, c0);
#pragma unroll
            for (int qi = 0; qi < 8; qi++)
                acc[hh][qi] = ffma2(acc[hh][qi], c2, kvp[qi]);
        }
    }
}

// grid (N, 4): 8 warps = 4 head-pairs x 2 chunks; chunks merged in-block.
__global__ __launch_bounds__(256) void flash_kernel(
    const float* __restrict__ qt, const float* __restrict__ qpart,
    const float* __restrict__ bq, const float* __restrict__ bk,
    const float* __restrict__ kv, const float* __restrict__ extra,
    const unsigned char* __restrict__ mask,
    float2* __restrict__ fst, float* __restrict__ facc,
    int Tlen, int Tmain, long rs)
{
    __shared__ __align__(16) float4 sacc[4][2][128];
    __shared__ float2 sms[4][2];
    int n = blockIdx.x;
    int w = threadIdx.x >> 5, lane = threadIdx.x & 31;
    int hp = w & 3, c = w >> 2, h0 = hp * 2;
    int e = blockIdx.y * 2 + c;
    int ts = (e * Tlen) >> 3, te = ((e + 1) * Tlen) >> 3;

    u64x2 qtr[2][8];
#pragma unroll
    for (int hh = 0; hh < 2; hh++) {
        const float4* qp = (const float4*)(qt + ((size_t)n * HH + h0 + hh) * DDIM);
#pragma unroll
        for (int qi = 0; qi < 4; qi++) {
            float4 v = qp[lane + 32 * qi];
            qtr[hh][2*qi] = pk2(v.x, v.y); qtr[hh][2*qi+1] = pk2(v.z, v.w);
        }
    }
    // qb[hh] = (0.125*(sum_s qpart + bq)) . bk over the head's 64 dims
    float qb[2];
#pragma unroll
    for (int hh = 0; hh < 2; hh++) {
        int d0 = (h0 + hh) * 64 + lane, d1 = d0 + 32;
        float v0 = bq[d0], v1 = bq[d1];
        for (int s = 0; s < 8; s++) {
            v0 += qpart[(size_t)s * PSD + (size_t)n * DDIM + d0];
            v1 += qpart[(size_t)s * PSD + (size_t)n * DDIM + d1];
        }
        float p = 0.125f * v0 * bk[d0] + 0.125f * v1 * bk[d1];
#pragma unroll
        for (int off = 16; off > 0; off >>= 1)
            p += __shfl_xor_sync(0xffffffffu, p, off);
        qb[hh] = p;
    }
    float mh[2] = {-1e30f, -1e30f}, sh[2] = {0.f, 0.f};
    u64x2 acc[2][8];
#pragma unroll
    for (int hh = 0; hh < 2; hh++)
#pragma unroll
        for (int qi = 0; qi < 8; qi++) acc[hh][qi] = pk2(0.f, 0.f);

    const float* kvn = kv + (size_t)n * DDIM;
    const float4* erow = (const float4*)(extra + (size_t)n * DDIM);
    const unsigned char* mk = mask ? mask + (size_t)n * Tlen : nullptr;

    u64x2 A[8], B[8];
    if (ts < te) f_load(A, kvn, erow, ts, Tmain, rs, lane);
    int t = ts;
    while (t < te) {
        if (t + 1 < te) f_load(B, kvn, erow, t + 1, Tmain, rs, lane);
        f_step(A, qtr, qb, (mk && mk[t]) ? -1e9f : 0.f, mh, sh, acc);
        t++;
        if (t >= te) break;
        if (t + 1 < te) f_load(A, kvn, erow, t + 1, Tmain, rs, lane);
        f_step(B, qtr, qb, (mk && mk[t]) ? -1e9f : 0.f, mh, sh, acc);
        t++;
    }

    // in-block merge of the two chunks (c=1 -> smem, c=0 combines)
    if (c == 1) {
#pragma unroll
        for (int hh = 0; hh < 2; hh++) {
            if (lane == 0) sms[hp][hh] = make_float2(mh[hh], sh[hh]);
#pragma unroll
            for (int qi = 0; qi < 4; qi++) {
                float2 a = upk(acc[hh][2*qi]), b = upk(acc[hh][2*qi+1]);
                float4 v = {a.x, a.y, b.x, b.y};
                sacc[hp][hh][lane + 32 * qi] = v;
            }
        }
    }
    __syncthreads();
    if (c == 0) {
#pragma unroll
        for (int hh = 0; hh < 2; hh++) {
            float2 o = sms[hp][hh];
            float M  = fmaxf(mh[hh], o.x);
            float e0 = __expf(mh[hh] - M), e1 = __expf(o.x - M);
            float S  = sh[hh] * e0 + o.y * e1;
            size_t base = ((size_t)n * 4 + blockIdx.y) * HH + h0 + hh;
            if (lane == 0) fst[base] = make_float2(M, S);
            float4* op = (float4*)(facc + base * DDIM);
#pragma unroll
            for (int qi = 0; qi < 4; qi++) {
                float2 a = upk(acc[hh][2*qi]), b = upk(acc[hh][2*qi+1]);
                float4 sv = sacc[hp][hh][lane + 32 * qi];
                float4 v;
                v.x = e0*a.x + e1*sv.x; v.y = e0*a.y + e1*sv.y;
                v.z = e0*b.x + e1*sv.z; v.w = e0*b.y + e1*sv.w;
                op[lane + 32 * qi] = v;
            }
        }
    }
}

// ---------------- host ----------------
static GP mkgp() { GP p; p.abias = nullptr; p.abOff = 0; p.ascale = 1.f;
    p.arelu = 0; p.fst = nullptr; p.aSeg = 0; p.ks2 = 0; p.aOffZ = 0;
    p.wOffZ = 0; p.cOffZ = 0; p.cSeg = 0; return p; }

extern "C" void kernel_launch(void* const* d_in, const int* in_sizes, int n_in,
                              void* d_out, int out_size)
{
    (void)in_sizes; (void)n_in; (void)out_size;
    const int*   toks   = (const int*)  d_in[0];
    const float* cached = (const float*)d_in[1];
    const float* memory = (const float*)d_in[2];
    const unsigned char* mmask = (const unsigned char*)d_in[3];
    const float* embd   = (const float*)d_in[4];
    const float* Wqkv_s = (const float*)d_in[5];
    const float* bqkv_s = (const float*)d_in[6];
    const float* Wo_s   = (const float*)d_in[7];
    const float* bo_s   = (const float*)d_in[8];
    const float* Wqkv_c = (const float*)d_in[9];
    const float* bqkv_c = (const float*)d_in[10];
    const float* Wo_c   = (const float*)d_in[11];
    const float* bo_c   = (const float*)d_in[12];
    const float* W1     = (const float*)d_in[13];
    const float* b1     = (const float*)d_in[14];
    const float* W2     = (const float*)d_in[15];
    const float* b2     = (const float*)d_in[16];
    const float* ln1w   = (const float*)d_in[17];
    const float* ln1b   = (const float*)d_in[18];
    const float* ln2w   = (const float*)d_in[19];
    const float* ln2b   = (const float*)d_in[20];
    const float* ln3w   = (const float*)d_in[21];
    const float* ln3b   = (const float*)d_in[22];
    const int*   offp   = (const int*)  d_in[23];
    float* dout = (float*)d_out;

    float *tgt, *qt, *partA, *partB, *facc; float2* fst;
    cudaGetSymbolAddress((void**)&tgt,   g_tgt);
    cudaGetSymbolAddress((void**)&qt,    g_qt);
    cudaGetSymbolAddress((void**)&partA, g_partA);
    cudaGetSymbolAddress((void**)&partB, g_partB);
    cudaGetSymbolAddress((void**)&facc,  g_facc);
    cudaGetSymbolAddress((void**)&fst,   g_fst);

    embed_kernel<<<NNH, 128>>>(toks, embd, offp, tgt);

    for (int l = 0; l < LL; l++) {
        for (int pass = 0; pass < 2; pass++) {
            const float* Wqkv = (pass==0 ? Wqkv_s : Wqkv_c) + (size_t)l*3*DDIM*DDIM;
            const float* bqkv = (pass==0 ? bqkv_s : bqkv_c) + (size_t)l*3*DDIM;
            const float* Wo   = (pass==0 ? Wo_s   : Wo_c)   + (size_t)l*DDIM*DDIM;
            const float* bo   = (pass==0 ? bo_s   : bo_c)   + (size_t)l*DDIM;
            const float* lw   = (pass==0 ? ln1w : ln2w) + (size_t)l*DDIM;
            const float* lb   = (pass==0 ? ln1b : ln2b) + (size_t)l*DDIM;
            const float* kv   = (pass==0) ? cached + (size_t)l*TT*NNH*DDIM : memory;
            int Tlen  = (pass==0) ? TT + 1 : SSL;
            int Tmain = (pass==0) ? TT : SSL;
            const unsigned char* mk = (pass==0) ? nullptr : mmask;

            // S1: q partials = tgt @ Wq^T  (raw, split-K 8)
            {
                GP p = mkgp();
                p.A = tgt; p.lda = DDIM;
                p.W = Wqkv; p.ldw = DDIM;
                p.C = partA; p.ldc = DDIM; p.cSeg = PSD;
                p.K = 64; p.KS = 8;
                gemm3<0,false><<<dim3(4,8,8),256>>>(p);
            }
            // S2: qt[n,h,:] = (0.125*(sum q-partials + bq))[h slice] @ Wk_h
            {
                GP p = mkgp();
                p.A = partA; p.lda = DDIM; p.aOffZ = DHH; p.aSeg = PSD; p.ks2 = 8;
                p.abias = bqkv; p.abOff = DHH; p.ascale = 0.125f;
                p.W = Wqkv + DDIM*DDIM; p.ldw = DDIM; p.wOffZ = DHH*DDIM;
                p.C = qt; p.ldc = HH*DDIM; p.cOffZ = DDIM;
                p.K = 64; p.KS = 1;
                gemm3<1,true><<<dim3(4,8,8),256>>>(p);
            }
            // S3: flash
            flash_kernel<<<dim3(NNH,4),256>>>(qt, partA, bqkv, bqkv + DDIM,
                                              kv, tgt, mk, fst, facc,
                                              Tlen, Tmain, (long)PSD);
            // S4: o partials = merged(ctx)[per-head] @ Wv_h^T  (split-K 8)
            {
                GP p = mkgp();
                p.A = facc; p.lda = 4*HH*DDIM; p.aOffZ = DDIM; p.aSeg = HH*DDIM;
                p.fst = fst;
                p.W = Wqkv + 2*DDIM*DDIM; p.ldw = DDIM; p.wOffZ = DHH*DDIM;
                p.C = partA; p.ldc = DDIM; p.cOffZ = DHH; p.cSeg = PSD;
                p.K = 64; p.KS = 8;
                gemm3<2,false><<<dim3(4,1,64),256>>>(p);
            }
            // S5: attn partials = (sum o-partials + bv) @ Wo^T  (split-K 8)
            {
                GP p = mkgp();
                p.A = partA; p.lda = DDIM; p.aSeg = PSD; p.ks2 = 8;
                p.abias = bqkv + 2*DDIM;
                p.W = Wo; p.ldw = DDIM;
                p.C = partB; p.ldc = DDIM; p.cSeg = PSD;
                p.K = 64; p.KS = 8;
                gemm3<1,false><<<dim3(4,8,8),256>>>(p);
            }
            // S6: reduce + bo + residual + LN
            ln_red_kernel<<<NNH,128>>>(partB, PSD, 8, bo, tgt, lw, lb, tgt);
        }
        // FFN
        const float* W1l = W1 + (size_t)l*DFF*DDIM;
        const float* W2l = W2 + (size_t)l*DDIM*DFF;
        {   // FFN1: hidden partials = tgt @ W1^T (raw, split-K 2)
            GP p = mkgp();
            p.A = tgt; p.lda = DDIM;
            p.W = W1l; p.ldw = DDIM;
            p.C = partA; p.ldc = DFF; p.cSeg = (long)NNH*DFF;
            p.K = 256; p.KS = 2;
            gemm3<0,false><<<dim3(4,32,2),256>>>(p);
        }
        {   // FFN2: out partials = relu(sum + b1) @ W2^T (split-K 8)
            GP p = mkgp();
            p.A = partA; p.lda = DFF; p.aSeg = (long)NNH*DFF; p.ks2 = 2;
            p.abias = b1 + (size_t)l*DFF; p.arelu = 1;
            p.W = W2l; p.ldw = DFF;
            p.C = partB; p.ldc = DDIM; p.cSeg = PSD;
            p.K = 256; p.KS = 8;
            gemm3<1,false><<<dim3(4,8,8),256>>>(p);
        }
        ln_red_kernel<<<NNH,128>>>(partB, PSD, 8, b2 + (size_t)l*DDIM, tgt,
                                   ln3w + (size_t)l*DDIM, ln3b + (size_t)l*DDIM,
                                   (l == LL-1) ? dout : tgt);
    }
}

// round 10
// speedup vs baseline: 1.2944x; 1.2944x over previous
#include <cuda_runtime.h>
#include <cuda_bf16.h>
#include <cstdint>
#include <cstddef>

#define LL   6
#define TT   256
#define NNH  128
#define DDIM 512
#define HH   8
#define DHH  64
#define DFF  2048
#define SSL  512
#define PSD  (NNH * DDIM)

// flash pipeline config
#define FSLOTS 5          // smem slots per warp (1 spare vs groups in flight)
#define FDEPTH 4          // cp.async groups in flight
#define FSMEM  (8 * FSLOTS * 2048)   // bytes of dynamic smem for flash

typedef unsigned long long u64x2;

__device__ __forceinline__ u64x2 pk2(float a, float b) {
    u64x2 r; asm("mov.b64 %0, {%1, %2};" : "=l"(r) : "f"(a), "f"(b)); return r;
}
__device__ __forceinline__ float2 upk(u64x2 v) {
    float2 r; asm("mov.b64 {%0, %1}, %2;" : "=f"(r.x), "=f"(r.y) : "l"(v)); return r;
}
__device__ __forceinline__ u64x2 ffma2(u64x2 a, u64x2 b, u64x2 c) {
    u64x2 d; asm("fma.rn.f32x2 %0, %1, %2, %3;" : "=l"(d) : "l"(a), "l"(b), "l"(c)); return d;
}
__device__ __forceinline__ uint32_t smem_u32(const void* p) {
    uint32_t a;
    asm("{ .reg .u64 t; cvta.to.shared.u64 t, %1; cvt.u32.u64 %0, t; }" : "=r"(a) : "l"(p));
    return a;
}
__device__ __forceinline__ void cp16(uint32_t dst, const void* src) {
    asm volatile("cp.async.cg.shared.global [%0], [%1], 16;" :: "r"(dst), "l"(src));
}
#define CP_COMMIT() asm volatile("cp.async.commit_group;" ::: "memory")
#define CP_WAIT(N)  asm volatile("cp.async.wait_group %0;" :: "n"(N) : "memory")

// scratch (__device__ globals; no allocation allowed)
__device__ float  g_tgt [NNH * DDIM];
__device__ float  g_q   [NNH * DDIM];
__device__ float  g_o   [NNH * DDIM];
__device__ float  g_qt  [NNH * HH * DDIM];
__device__ float  g_ctx [NNH * HH * DDIM];
__device__ float  g_part[8 * NNH * DDIM];      // also covers 2 slabs of N*DFF
__device__ float  g_facc[NNH * 8 * HH * DDIM];
__device__ float2 g_fst [NNH * 8 * HH];

// ---------------- embedding + positional encoding ----------------
__global__ __launch_bounds__(128) void embed_kernel(
    const int* __restrict__ toks, const float* __restrict__ embd,
    const int* __restrict__ offp, float* __restrict__ out)
{
    int n = blockIdx.x, tid = threadIdx.x;
    const float* erow = embd + (size_t)toks[n] * DDIM;
    float off = (float)offp[0];
    const float c = -9.210340371976184f / (float)DDIM;
    float4 v;
#pragma unroll
    for (int j = 0; j < 4; j++) {
        int d = tid * 4 + j;
        float ang = off * expf((float)(d & ~1) * c);
        ((float*)&v)[j] = erow[d] + ((d & 1) ? cosf(ang) : sinf(ang));
    }
    *(float4*)(out + (size_t)n * DDIM + tid * 4) = v;
}

// ---------------- GEMM (R7 form): 32x64 tile, double-buffered ----------------
#define KC 16
template<bool WT>
__global__ __launch_bounds__(256) void gemm_kernel(
    const float* __restrict__ A, int lda, int aOffZ,
    const float* __restrict__ W, int ldw, int wOffZ,
    float* __restrict__ C, int ldc, int cOffZ, long partStride,
    const float* __restrict__ bias, int K, int KS, float scale, int relu)
{
    __shared__ __align__(16) float As[2][KC][34];
    __shared__ __align__(16) float Ws[2][KC][68];
    int z = blockIdx.z, h = z / KS, ks = z - h * KS;
    long koff = (long)ks * K;
    A += (size_t)h * aOffZ + koff;
    W += (size_t)h * wOffZ + (WT ? (size_t)koff * ldw : (size_t)koff);
    C += (size_t)h * cOffZ + (size_t)ks * partStride;
    int n0 = blockIdx.x * 32, m0 = blockIdx.y * 64;
    int t = threadIdx.x, tx = t & 15, ty = t >> 4;

    int ar  = t >> 3, ak  = (t & 7) * 2;
    int wr  = t >> 2, wk  = (t & 3) * 4;
    int wtk = t >> 4, wtm = (t & 15) * 4;

    u64x2 acc[2][2];
    acc[0][0] = acc[0][1] = acc[1][0] = acc[1][1] = pk2(0.f, 0.f);

    float2 ra = *(const float2*)&A[(size_t)(n0 + ar) * lda + ak];
    float4 rw;
    if (WT) rw = *(const float4*)&W[(size_t)wtk * ldw + m0 + wtm];
    else    rw = *(const float4*)&W[(size_t)(m0 + wr) * ldw + wk];

    int buf = 0;
    for (int kc = 0; kc < K; kc += KC) {
        As[buf][ak + 0][ar] = ra.x;
        As[buf][ak + 1][ar] = ra.y;
        if (WT) {
            *(float4*)&Ws[buf][wtk][wtm] = rw;
        } else {
            Ws[buf][wk + 0][wr] = rw.x; Ws[buf][wk + 1][wr] = rw.y;
            Ws[buf][wk + 2][wr] = rw.z; Ws[buf][wk + 3][wr] = rw.w;
        }
        __syncthreads();
        int kn = kc + KC;
        if (kn < K) {
            ra = *(const float2*)&A[(size_t)(n0 + ar) * lda + kn + ak];
            if (WT) rw = *(const float4*)&W[(size_t)(kn + wtk) * ldw + m0 + wtm];
            else    rw = *(const float4*)&W[(size_t)(m0 + wr) * ldw + kn + wk];
        }
#pragma unroll
        for (int kk = 0; kk < KC; kk++) {
            float2 av = *(const float2*)&As[buf][kk][ty * 2];
            u64x2 w0 = *(const u64x2*)&Ws[buf][kk][tx * 4];
            u64x2 w1 = *(const u64x2*)&Ws[buf][kk][tx * 4 + 2];
            u64x2 a0 = pk2(av.x, av.x), a1 = pk2(av.y, av.y);
            acc[0][0] = ffma2(a0, w0, acc[0][0]);
            acc[0][1] = ffma2(a0, w1, acc[0][1]);
            acc[1][0] = ffma2(a1, w0, acc[1][0]);
            acc[1][1] = ffma2(a1, w1, acc[1][1]);
        }
        buf ^= 1;
    }

    int mc = m0 + tx * 4;
#pragma unroll
    for (int i = 0; i < 2; i++) {
        int row = n0 + ty * 2 + i;
        float2 f0 = upk(acc[i][0]), f1 = upk(acc[i][1]);
        float out[4] = {f0.x, f0.y, f1.x, f1.y};
#pragma unroll
        for (int j = 0; j < 4; j++) {
            if (bias) out[j] += bias[mc + j];
            out[j] *= scale;
            if (relu) out[j] = fmaxf(out[j], 0.f);
        }
        float4 v = {out[0], out[1], out[2], out[3]};
        *(float4*)&C[(size_t)row * ldc + mc] = v;
    }
}

// split-K reduce: C = relu(scale*(sum_ks part + bias)) + res
__global__ __launch_bounds__(128) void reduce_kernel(
    const float* __restrict__ part, long PS, int KS,
    const float* __restrict__ bias, const float* __restrict__ res,
    float* __restrict__ C, int M, float scale, int relu)
{
    size_t idx = ((size_t)blockIdx.x * 128 + threadIdx.x) * 4;
    int mcol = (int)(idx % M);
    float4 v = make_float4(0.f, 0.f, 0.f, 0.f);
    for (int ks = 0; ks < KS; ks++) {
        float4 p = *(const float4*)(part + (size_t)ks * PS + idx);
        v.x += p.x; v.y += p.y; v.z += p.z; v.w += p.w;
    }
    if (bias) {
        float4 bb = *(const float4*)(bias + mcol);
        v.x += bb.x; v.y += bb.y; v.z += bb.z; v.w += bb.w;
    }
    v.x *= scale; v.y *= scale; v.z *= scale; v.w *= scale;
    if (relu) {
        v.x = fmaxf(v.x, 0.f); v.y = fmaxf(v.y, 0.f);
        v.z = fmaxf(v.z, 0.f); v.w = fmaxf(v.w, 0.f);
    }
    if (res) {
        float4 r = *(const float4*)(res + idx);
        v.x += r.x; v.y += r.y; v.z += r.z; v.w += r.w;
    }
    *(float4*)(C + idx) = v;
}

// fused split-K reduce + bias + residual + layernorm (block per row)
__global__ __launch_bounds__(128) void ln_red_kernel(
    const float* __restrict__ part, long PS, int KS,
    const float* __restrict__ bias, const float* __restrict__ res,
    const float* __restrict__ w, const float* __restrict__ b,
    float* __restrict__ out)
{
    int n = blockIdx.x, t = threadIdx.x, warp = t >> 5, lane = t & 31;
    size_t idx = (size_t)n * DDIM + t * 4;
    float4 xv = make_float4(0.f, 0.f, 0.f, 0.f);
    for (int ks = 0; ks < KS; ks++) {
        float4 p = *(const float4*)(part + (size_t)ks * PS + idx);
        xv.x += p.x; xv.y += p.y; xv.z += p.z; xv.w += p.w;
    }
    float4 bb = *(const float4*)(bias + t * 4);
    float4 rr = *(const float4*)(res + idx);
    xv.x += bb.x + rr.x; xv.y += bb.y + rr.y;
    xv.z += bb.z + rr.z; xv.w += bb.w + rr.w;

    float s  = xv.x + xv.y + xv.z + xv.w;
    float sq = xv.x*xv.x + xv.y*xv.y + xv.z*xv.z + xv.w*xv.w;
#pragma unroll
    for (int off = 16; off > 0; off >>= 1) {
        s  += __shfl_xor_sync(0xffffffffu, s,  off);
        sq += __shfl_xor_sync(0xffffffffu, sq, off);
    }
    __shared__ float2 rb[4];
    if (lane == 0) rb[warp] = make_float2(s, sq);
    __syncthreads();
    float S = 0.f, Q = 0.f;
#pragma unroll
    for (int i = 0; i < 4; i++) { S += rb[i].x; Q += rb[i].y; }
    float mean = S * (1.0f / DDIM);
    float var  = Q * (1.0f / DDIM) - mean * mean;
    float r = rsqrtf(var + 1e-5f);
    float4 wv = *(const float4*)(w + t * 4);
    float4 bv = *(const float4*)(b + t * 4);
    float4 o;
    o.x = (xv.x - mean) * r * wv.x + bv.x;
    o.y = (xv.y - mean) * r * wv.y + bv.y;
    o.z = (xv.z - mean) * r * wv.z + bv.z;
    o.w = (xv.w - mean) * r * wv.w + bv.w;
    *(float4*)(out + idx) = o;
}

// ---------------- flash attention: cp.async-pipelined kv stream ----------------
__device__ __forceinline__ void f_loads(u64x2* dst, const float* rowp, int lane)
{
    const float4* rp = (const float4*)rowp;
#pragma unroll
    for (int qi = 0; qi < 4; qi++) {
        float4 v = rp[lane + 32 * qi];
        dst[2*qi] = pk2(v.x, v.y); dst[2*qi+1] = pk2(v.z, v.w);
    }
}
__device__ __forceinline__ void f_step(const u64x2* kvp, const u64x2 qtr[2][8],
    const float qb[2], float nm, float mh[2], float sh[2], u64x2 acc[2][8])
{
    float sc[2];
#pragma unroll
    for (int hh = 0; hh < 2; hh++) {
        u64x2 d0 = pk2(0.f, 0.f), d1 = pk2(0.f, 0.f);
#pragma unroll
        for (int qi = 0; qi < 4; qi++) {
            d0 = ffma2(qtr[hh][2*qi],   kvp[2*qi],   d0);
            d1 = ffma2(qtr[hh][2*qi+1], kvp[2*qi+1], d1);
        }
        float2 f0 = upk(d0), f1 = upk(d1);
        sc[hh] = f0.x + f0.y + f1.x + f1.y;
    }
#pragma unroll
    for (int off = 16; off > 0; off >>= 1) {
        sc[0] += __shfl_xor_sync(0xffffffffu, sc[0], off);
        sc[1] += __shfl_xor_sync(0xffffffffu, sc[1], off);
    }
#pragma unroll
    for (int hh = 0; hh < 2; hh++) {
        float s = sc[hh] + qb[hh] + nm;
        if (s <= mh[hh]) {               // warp-uniform branch
            float p = __expf(s - mh[hh]);
            sh[hh] += p;
            u64x2 p2 = pk2(p, p);
#pragma unroll
            for (int qi = 0; qi < 8; qi++)
                acc[hh][qi] = ffma2(kvp[qi], p2, acc[hh][qi]);
        } else {
            float c0 = __expf(mh[hh] - s);
            sh[hh] = sh[hh] * c0 + 1.f;
            mh[hh] = s;
            u64x2 c2 = pk2(c0, c0);
#pragma unroll
            for (int qi = 0; qi < 8; qi++)
                acc[hh][qi] = ffma2(acc[hh][qi], c2, kvp[qi]);
        }
    }
}

// grid (N, 4), 256 thr = 8 warps: 4 head-pairs x 2 t-chunks -> 8 segments.
__global__ __launch_bounds__(256) void flash_kernel(
    const float* __restrict__ qt, const float* __restrict__ qs,
    const float* __restrict__ bk, const float* __restrict__ kv,
    const float* __restrict__ extra, const unsigned char* __restrict__ mask,
    float2* __restrict__ fst, float* __restrict__ facc,
    int Tlen, int Tmain, long rs)
{
    extern __shared__ __align__(16) float fsm[];   // 8 warps * FSLOTS * 512 floats
    int n = blockIdx.x;
    int w = threadIdx.x >> 5, lane = threadIdx.x & 31;
    int hp = w & 3, c = w >> 2, h0 = hp * 2;
    int seg = blockIdx.y * 2 + c;
    int ts = (seg * Tlen) >> 3, te = ((seg + 1) * Tlen) >> 3;

    float* ring = fsm + (size_t)w * (FSLOTS * 512);
    uint32_t ring_s = smem_u32(ring);

    u64x2 qtr[2][8];
#pragma unroll
    for (int hh = 0; hh < 2; hh++) {
        const float4* qp = (const float4*)(qt + ((size_t)n * HH + h0 + hh) * DDIM);
#pragma unroll
        for (int qi = 0; qi < 4; qi++) {
            float4 v = qp[lane + 32 * qi];
            qtr[hh][2*qi] = pk2(v.x, v.y); qtr[hh][2*qi+1] = pk2(v.z, v.w);
        }
    }
    float qb[2];
#pragma unroll
    for (int hh = 0; hh < 2; hh++) {
        int h = h0 + hh;
        float p = qs[(size_t)n * DDIM + h*64 + lane]      * bk[h*64 + lane]
                + qs[(size_t)n * DDIM + h*64 + 32 + lane] * bk[h*64 + 32 + lane];
#pragma unroll
        for (int off = 16; off > 0; off >>= 1)
            p += __shfl_xor_sync(0xffffffffu, p, off);
        qb[hh] = p;
    }
    float mh[2] = {-1e30f, -1e30f}, sh[2] = {0.f, 0.f};
    u64x2 acc[2][8];
#pragma unroll
    for (int hh = 0; hh < 2; hh++)
#pragma unroll
        for (int qi = 0; qi < 8; qi++) acc[hh][qi] = pk2(0.f, 0.f);

    const float* kvn = kv + (size_t)n * DDIM;
    const float* erow = extra + (size_t)n * DDIM;
    const unsigned char* mk = mask ? mask + (size_t)n * Tlen : nullptr;

    // issue row t into slot (t-ts)%FSLOTS; always commit (keeps group count aligned)
    auto issue = [&](int t) {
        if (t < te) {
            const float* sp = ((t < Tmain) ? (kvn + (size_t)t * rs) : erow) + lane * 16;
            uint32_t d = ring_s + (uint32_t)((t - ts) % FSLOTS) * 2048u + (uint32_t)lane * 64u;
            cp16(d,      sp);
            cp16(d + 16, sp + 4);
            cp16(d + 32, sp + 8);
            cp16(d + 48, sp + 12);
        }
        CP_COMMIT();
    };

#pragma unroll
    for (int i = 0; i < FDEPTH; i++) issue(ts + i);

    u64x2 kvp[8];
    for (int t = ts; t < te; t++) {
        CP_WAIT(FDEPTH - 1);
        __syncwarp();
        f_loads(kvp, ring + ((t - ts) % FSLOTS) * 512, lane);
        issue(t + FDEPTH);
        f_step(kvp, qtr, qb, (mk && mk[t]) ? -1e9f : 0.f, mh, sh, acc);
    }
    CP_WAIT(0);

#pragma unroll
    for (int hh = 0; hh < 2; hh++) {
        size_t base = ((size_t)n * 8 + seg) * HH + h0 + hh;
        if (lane == 0) fst[base] = make_float2(mh[hh], sh[hh]);
        float4* op = (float4*)(facc + base * DDIM);
#pragma unroll
        for (int qi = 0; qi < 4; qi++) {
            float2 a = upk(acc[hh][2*qi]), b = upk(acc[hh][2*qi+1]);
            float4 v = {a.x, a.y, b.x, b.y};
            op[lane + 32 * qi] = v;
        }
    }
}

__global__ __launch_bounds__(256) void merge_kernel(
    const float* __restrict__ facc, const float2* __restrict__ fst,
    float* __restrict__ ctx)
{
    int n = blockIdx.x, w = threadIdx.x >> 5, lane = threadIdx.x & 31;
    float2 st[8]; float M = -1e30f;
#pragma unroll
    for (int s = 0; s < 8; s++) {
        st[s] = fst[((size_t)n * 8 + s) * HH + w];
        M = fmaxf(M, st[s].x);
    }
    float S = 0.f;
#pragma unroll
    for (int s = 0; s < 8; s++) S += st[s].y * __expf(st[s].x - M);
    float inv = 1.f / S;
    float co[8];
#pragma unroll
    for (int s = 0; s < 8; s++) co[s] = __expf(st[s].x - M) * inv;
    float4 out[4];
#pragma unroll
    for (int qi = 0; qi < 4; qi++) out[qi] = make_float4(0.f, 0.f, 0.f, 0.f);
#pragma unroll
    for (int s = 0; s < 8; s++) {
        const float4* ap = (const float4*)(facc + (((size_t)n * 8 + s) * HH + w) * DDIM);
#pragma unroll
        for (int qi = 0; qi < 4; qi++) {
            float4 v = ap[lane + 32 * qi];
            out[qi].x += co[s]*v.x; out[qi].y += co[s]*v.y;
            out[qi].z += co[s]*v.z; out[qi].w += co[s]*v.w;
        }
    }
    float4* op = (float4*)(ctx + ((size_t)n * HH + w) * DDIM);
#pragma unroll
    for (int qi = 0; qi < 4; qi++) op[lane + 32 * qi] = out[qi];
}

// ---------------- host ----------------
static void gemm(const float* A, int lda, int aOffZ,
                 const float* W, int ldw, int wOffZ, bool wt,
                 float* C, int ldc, int cOffZ, long PS, const float* bias,
                 int Kloc, int KS, int Hz, int Mz, float scale, int relu)
{
    dim3 g(4, Mz / 64, Hz * KS);
    if (wt)
        gemm_kernel<true><<<g,256>>>(A,lda,aOffZ,W,ldw,wOffZ,C,ldc,cOffZ,PS,bias,Kloc,KS,scale,relu);
    else
        gemm_kernel<false><<<g,256>>>(A,lda,aOffZ,W,ldw,wOffZ,C,ldc,cOffZ,PS,bias,Kloc,KS,scale,relu);
}
static void red(const float* part, long PS, int KS, const float* bias,
                const float* res, float* C, int M, float scale, int relu)
{
    reduce_kernel<<<(NNH * M) / 512, 128>>>(part, PS, KS, bias, res, C, M, scale, relu);
}

extern "C" void kernel_launch(void* const* d_in, const int* in_sizes, int n_in,
                              void* d_out, int out_size)
{
    (void)in_sizes; (void)n_in; (void)out_size;
    const int*   toks   = (const int*)  d_in[0];
    const float* cached = (const float*)d_in[1];
    const float* memory = (const float*)d_in[2];
    const unsigned char* mmask = (const unsigned char*)d_in[3];
    const float* embd   = (const float*)d_in[4];
    const float* Wqkv_s = (const float*)d_in[5];
    const float* bqkv_s = (const float*)d_in[6];
    const float* Wo_s   = (const float*)d_in[7];
    const float* bo_s   = (const float*)d_in[8];
    const float* Wqkv_c = (const float*)d_in[9];
    const float* bqkv_c = (const float*)d_in[10];
    const float* Wo_c   = (const float*)d_in[11];
    const float* bo_c   = (const float*)d_in[12];
    const float* W1     = (const float*)d_in[13];
    const float* b1     = (const float*)d_in[14];
    const float* W2     = (const float*)d_in[15];
    const float* b2     = (const float*)d_in[16];
    const float* ln1w   = (const float*)d_in[17];
    const float* ln1b   = (const float*)d_in[18];
    const float* ln2w   = (const float*)d_in[19];
    const float* ln2b   = (const float*)d_in[20];
    const float* ln3w   = (const float*)d_in[21];
    const float* ln3b   = (const float*)d_in[22];
    const int*   offp   = (const int*)  d_in[23];
    float* dout = (float*)d_out;

    float *tgt,*q,*o,*qt,*ctx,*part,*facc; float2* fst;
    cudaGetSymbolAddress((void**)&tgt,  g_tgt);
    cudaGetSymbolAddress((void**)&q,    g_q);
    cudaGetSymbolAddress((void**)&o,    g_o);
    cudaGetSymbolAddress((void**)&qt,   g_qt);
    cudaGetSymbolAddress((void**)&ctx,  g_ctx);
    cudaGetSymbolAddress((void**)&part, g_part);
    cudaGetSymbolAddress((void**)&facc, g_facc);
    cudaGetSymbolAddress((void**)&fst,  g_fst);

    cudaFuncSetAttribute(flash_kernel,
                         cudaFuncAttributeMaxDynamicSharedMemorySize, FSMEM);

    const long PS_D = (long)NNH * DDIM;
    embed_kernel<<<NNH, 128>>>(toks, embd, offp, tgt);

    for (int l = 0; l < LL; l++) {
        for (int pass = 0; pass < 2; pass++) {
            const float* Wqkv = (pass==0 ? Wqkv_s : Wqkv_c) + (size_t)l*3*DDIM*DDIM;
            const float* bqkv = (pass==0 ? bqkv_s : bqkv_c) + (size_t)l*3*DDIM;
            const float* Wo   = (pass==0 ? Wo_s   : Wo_c)   + (size_t)l*DDIM*DDIM;
            const float* bo   = (pass==0 ? bo_s   : bo_c)   + (size_t)l*DDIM;
            const float* lw   = (pass==0 ? ln1w : ln2w) + (size_t)l*DDIM;
            const float* lb   = (pass==0 ? ln1b : ln2b) + (size_t)l*DDIM;
            const float* kv   = (pass==0) ? cached + (size_t)l*TT*NNH*DDIM : memory;
            int Tlen  = (pass==0) ? TT + 1 : SSL;
            int Tmain = (pass==0) ? TT : SSL;
            const unsigned char* mk = (pass==0) ? nullptr : mmask;

            // q = 0.125*(tgt @ Wq^T + bq), split-K 4
            gemm(tgt, DDIM,0, Wqkv, DDIM,0,false, part, DDIM,0, PS_D, nullptr,
                 DDIM/4,4, 1, DDIM, 1.f,0);
            red(part, PS_D, 4, bqkv, nullptr, q, DDIM, 0.125f, 0);
            // qt[n,h,:] = q[n,h*64:(h+1)*64] @ Wk_h  (WT path, z=head)
            gemm(q, DDIM, DHH, Wqkv + DDIM*DDIM, DDIM, DHH*DDIM, true,
                 qt, HH*DDIM, DDIM, 0, nullptr, DHH,1, HH, DDIM, 1.f,0);
            // flash (cp.async pipelined) + merge -> ctx
            flash_kernel<<<dim3(NNH,4),256,FSMEM>>>(qt, q, bqkv + DDIM, kv, tgt, mk,
                                                    fst, facc, Tlen, Tmain, PS_D);
            merge_kernel<<<NNH,256>>>(facc, fst, ctx);
            // o[n, h*64+j] = Wv_h @ ctx[n,h,:] + bv, split-K 4 per head
            gemm(ctx, HH*DDIM, DDIM, Wqkv + 2*DDIM*DDIM, DDIM, DHH*DDIM, false,
                 part, DDIM, DHH, PS_D, nullptr, DDIM/4, 4, HH, DHH, 1.f, 0);
            red(part, PS_D, 4, bqkv + 2*DDIM, nullptr, o, DDIM, 1.f, 0);
            // attn = o @ Wo^T + bo + tgt, split-K 4, fused reduce+residual+LN
            gemm(o, DDIM,0, Wo, DDIM,0,false, part, DDIM,0, PS_D, nullptr,
                 DDIM/4,4, 1, DDIM, 1.f,0);
            ln_red_kernel<<<NNH,128>>>(part, PS_D, 4, bo, tgt, lw, lb, tgt);
        }
        // FFN
        const float* W1l = W1 + (size_t)l*DFF*DDIM;
        const float* W2l = W2 + (size_t)l*DDIM*DFF;
        gemm(tgt, DDIM,0, W1l, DDIM,0,false, part, DFF,0, (long)NNH*DFF, nullptr,
             DDIM/2,2, 1, DFF, 1.f,0);
        red(part, (long)NNH*DFF, 2, b1 + (size_t)l*DFF, nullptr,
            part + 2*(size_t)NNH*DFF, DFF, 1.f, 1);
        gemm(part + 2*(size_t)NNH*DFF, DFF,0, W2l, DFF,0,false, part, DDIM,0, PS_D, nullptr,
             DFF/8,8, 1, DDIM, 1.f,0);
        ln_red_kernel<<<NNH,128>>>(part, PS_D, 8, b2 + (size_t)l*DDIM, tgt,
                                   ln3w + (size_t)l*DDIM, ln3b + (size_t)l*DDIM,
                                   (l == LL-1) ? dout : tgt);
    }
}

// round 15
// speedup vs baseline: 1.3064x; 1.0092x over previous
#include <cuda_runtime.h>
#include <cuda_bf16.h>
#include <cstdint>
#include <cstddef>

#define LL   6
#define TT   256
#define NNH  128
#define DDIM 512
#define HH   8
#define DHH  64
#define DFF  2048
#define SSL  512
#define PSD  (NNH * DDIM)

#define FSLOTS 5
#define FDEPTH 4
#define FSMEM  (8 * FSLOTS * 2048)

typedef unsigned long long u64x2;

__device__ __forceinline__ u64x2 pk2(float a, float b) {
    u64x2 r; asm("mov.b64 %0, {%1, %2};" : "=l"(r) : "f"(a), "f"(b)); return r;
}
__device__ __forceinline__ float2 upk(u64x2 v) {
    float2 r; asm("mov.b64 {%0, %1}, %2;" : "=f"(r.x), "=f"(r.y) : "l"(v)); return r;
}
__device__ __forceinline__ u64x2 ffma2(u64x2 a, u64x2 b, u64x2 c) {
    u64x2 d; asm("fma.rn.f32x2 %0, %1, %2, %3;" : "=l"(d) : "l"(a), "l"(b), "l"(c)); return d;
}
__device__ __forceinline__ uint32_t smem_u32(const void* p) {
    uint32_t a;
    asm("{ .reg .u64 t; cvta.to.shared.u64 t, %1; cvt.u32.u64 %0, t; }" : "=r"(a) : "l"(p));
    return a;
}
__device__ __forceinline__ void cp16(uint32_t dst, const void* src) {
    asm volatile("cp.async.cg.shared.global [%0], [%1], 16;" :: "r"(dst), "l"(src));
}
#define CP_COMMIT() asm volatile("cp.async.commit_group;" ::: "memory")
#define CP_WAIT(N)  asm volatile("cp.async.wait_group %0;" :: "n"(N) : "memory")

// scratch (__device__ globals; no allocation allowed)
__device__ float  g_tgt [NNH * DDIM];
__device__ float  g_q   [NNH * DDIM];
__device__ float  g_o   [NNH * DDIM];
__device__ float  g_qt  [NNH * HH * DDIM];
__device__ float  g_ctx [NNH * HH * DDIM];
__device__ float  g_part[8 * NNH * DDIM];      // == 2 slabs of N*DFF exactly
__device__ float  g_facc[NNH * 8 * HH * DDIM]; // flash partials; also hosts ff
__device__ float2 g_fst [NNH * 8 * HH];

// ---------------- embedding + positional encoding ----------------
__global__ __launch_bounds__(128) void embed_kernel(
    const int* __restrict__ toks, const float* __restrict__ embd,
    const int* __restrict__ offp, float* __restrict__ out)
{
    int n = blockIdx.x, tid = threadIdx.x;
    const float* erow = embd + (size_t)toks[n] * DDIM;
    float off = (float)offp[0];
    const float c = -9.210340371976184f / (float)DDIM;
    float4 v;
#pragma unroll
    for (int j = 0; j < 4; j++) {
        int d = tid * 4 + j;
        float ang = off * expf((float)(d & ~1) * c);
        ((float*)&v)[j] = erow[d] + ((d & 1) ? cosf(ang) : sinf(ang));
    }
    *(float4*)(out + (size_t)n * DDIM + tid * 4) = v;
}

// ---------------- GEMM: 32x64 tile, 2-deep LDG prefetch ----------------
#define KC 16
template<bool WT>
__global__ __launch_bounds__(256) void gemm_kernel(
    const float* __restrict__ A, int lda, int aOffZ,
    const float* __restrict__ W, int ldw, int wOffZ,
    float* __restrict__ C, int ldc, int cOffZ, long partStride,
    const float* __restrict__ bias, int K, int KS, float scale, int relu)
{
    __shared__ __align__(16) float As[2][KC][34];
    __shared__ __align__(16) float Ws[2][KC][68];
    int z = blockIdx.z, h = z / KS, ks = z - h * KS;
    long koff = (long)ks * K;
    A += (size_t)h * aOffZ + koff;
    W += (size_t)h * wOffZ + (WT ? (size_t)koff * ldw : (size_t)koff);
    C += (size_t)h * cOffZ + (size_t)ks * partStride;
    int n0 = blockIdx.x * 32, m0 = blockIdx.y * 64;
    int t = threadIdx.x, tx = t & 15, ty = t >> 4;

    int ar  = t >> 3, ak  = (t & 7) * 2;
    int wr  = t >> 2, wk  = (t & 3) * 4;
    int wtk = t >> 4, wtm = (t & 15) * 4;

    auto loadA = [&](int i) -> float2 {
        return *(const float2*)&A[(size_t)(n0 + ar) * lda + i * KC + ak];
    };
    auto loadW = [&](int i) -> float4 {
        if (WT) return *(const float4*)&W[(size_t)(i * KC + wtk) * ldw + m0 + wtm];
        else    return *(const float4*)&W[(size_t)(m0 + wr) * ldw + i * KC + wk];
    };

    u64x2 acc[2][2];
    acc[0][0] = acc[0][1] = acc[1][0] = acc[1][1] = pk2(0.f, 0.f);

    int nch = K / KC;
    float2 raR[2]; float4 rwR[2];
    raR[0] = loadA(0); rwR[0] = loadW(0);
    if (nch > 1) { raR[1] = loadA(1); rwR[1] = loadW(1); }

    for (int i = 0; i < nch; i++) {
        int b = i & 1;
        As[b][ak + 0][ar] = raR[b].x;
        As[b][ak + 1][ar] = raR[b].y;
        if (WT) {
            *(float4*)&Ws[b][wtk][wtm] = rwR[b];
        } else {
            Ws[b][wk + 0][wr] = rwR[b].x; Ws[b][wk + 1][wr] = rwR[b].y;
            Ws[b][wk + 2][wr] = rwR[b].z; Ws[b][wk + 3][wr] = rwR[b].w;
        }
        if (i + 2 < nch) { raR[b] = loadA(i + 2); rwR[b] = loadW(i + 2); }
        __syncthreads();
#pragma unroll
        for (int kk = 0; kk < KC; kk++) {
            float2 av = *(const float2*)&As[b][kk][ty * 2];
            u64x2 w0 = *(const u64x2*)&Ws[b][kk][tx * 4];
            u64x2 w1 = *(const u64x2*)&Ws[b][kk][tx * 4 + 2];
            u64x2 a0 = pk2(av.x, av.x), a1 = pk2(av.y, av.y);
            acc[0][0] = ffma2(a0, w0, acc[0][0]);
            acc[0][1] = ffma2(a0, w1, acc[0][1]);
            acc[1][0] = ffma2(a1, w0, acc[1][0]);
            acc[1][1] = ffma2(a1, w1, acc[1][1]);
        }
    }

    int mc = m0 + tx * 4;
#pragma unroll
    for (int i = 0; i < 2; i++) {
        int row = n0 + ty * 2 + i;
        float2 f0 = upk(acc[i][0]), f1 = upk(acc[i][1]);
        float out[4] = {f0.x, f0.y, f1.x, f1.y};
#pragma unroll
        for (int j = 0; j < 4; j++) {
            if (bias) out[j] += bias[mc + j];
            out[j] *= scale;
            if (relu) out[j] = fmaxf(out[j], 0.f);
        }
        float4 v = {out[0], out[1], out[2], out[3]};
        *(float4*)&C[(size_t)row * ldc + mc] = v;
    }
}

// split-K reduce: C = relu(scale*(sum_ks part + bias)) + res
__global__ __launch_bounds__(128) void reduce_kernel(
    const float* __restrict__ part, long PS, int KS,
    const float* __restrict__ bias, const float* __restrict__ res,
    float* __restrict__ C, int M, float scale, int relu)
{
    size_t idx = ((size_t)blockIdx.x * 128 + threadIdx.x) * 4;
    int mcol = (int)(idx % M);
    float4 v = make_float4(0.f, 0.f, 0.f, 0.f);
    for (int ks = 0; ks < KS; ks++) {
        float4 p = *(const float4*)(part + (size_t)ks * PS + idx);
        v.x += p.x; v.y += p.y; v.z += p.z; v.w += p.w;
    }
    if (bias) {
        float4 bb = *(const float4*)(bias + mcol);
        v.x += bb.x; v.y += bb.y; v.z += bb.z; v.w += bb.w;
    }
    v.x *= scale; v.y *= scale; v.z *= scale; v.w *= scale;
    if (relu) {
        v.x = fmaxf(v.x, 0.f); v.y = fmaxf(v.y, 0.f);
        v.z = fmaxf(v.z, 0.f); v.w = fmaxf(v.w, 0.f);
    }
    if (res) {
        float4 r = *(const float4*)(res + idx);
        v.x += r.x; v.y += r.y; v.z += r.z; v.w += r.w;
    }
    *(float4*)(C + idx) = v;
}

// fused split-K reduce + bias + residual + layernorm (block per row)
__global__ __launch_bounds__(128) void ln_red_kernel(
    const float* __restrict__ part, long PS, int KS,
    const float* __restrict__ bias, const float* __restrict__ res,
    const float* __restrict__ w, const float* __restrict__ b,
    float* __restrict__ out)
{
    int n = blockIdx.x, t = threadIdx.x, warp = t >> 5, lane = t & 31;
    size_t idx = (size_t)n * DDIM + t * 4;
    float4 xv = make_float4(0.f, 0.f, 0.f, 0.f);
    for (int ks = 0; ks < KS; ks++) {
        float4 p = *(const float4*)(part + (size_t)ks * PS + idx);
        xv.x += p.x; xv.y += p.y; xv.z += p.z; xv.w += p.w;
    }
    float4 bb = *(const float4*)(bias + t * 4);
    float4 rr = *(const float4*)(res + idx);
    xv.x += bb.x + rr.x; xv.y += bb.y + rr.y;
    xv.z += bb.z + rr.z; xv.w += bb.w + rr.w;

    float s  = xv.x + xv.y + xv.z + xv.w;
    float sq = xv.x*xv.x + xv.y*xv.y + xv.z*xv.z + xv.w*xv.w;
#pragma unroll
    for (int off = 16; off > 0; off >>= 1) {
        s  += __shfl_xor_sync(0xffffffffu, s,  off);
        sq += __shfl_xor_sync(0xffffffffu, sq, off);
    }
    __shared__ float2 rb[4];
    if (lane == 0) rb[warp] = make_float2(s, sq);
    __syncthreads();
    float S = 0.f, Q = 0.f;
#pragma unroll
    for (int i = 0; i < 4; i++) { S += rb[i].x; Q += rb[i].y; }
    float mean = S * (1.0f / DDIM);
    float var  = Q * (1.0f / DDIM) - mean * mean;
    float r = rsqrtf(var + 1e-5f);
    float4 wv = *(const float4*)(w + t * 4);
    float4 bv = *(const float4*)(b + t * 4);
    float4 o;
    o.x = (xv.x - mean) * r * wv.x + bv.x;
    o.y = (xv.y - mean) * r * wv.y + bv.y;
    o.z = (xv.z - mean) * r * wv.z + bv.z;
    o.w = (xv.w - mean) * r * wv.w + bv.w;
    *(float4*)(out + idx) = o;
}

// ---------------- flash attention: swizzled cp.async ring ----------------
// smem layout within each 2KB row slot: 16B chunk g (0..127) stored at
// position (g & ~31) | ((g&31) ^ (((g>>3)&3)<<2))  -> conflict-free LDS.128.
__device__ __forceinline__ void f_loads(u64x2* dst, const float* slot, int lane)
{
    uint32_t ls = (uint32_t)lane ^ ((((uint32_t)lane >> 3) & 3u) << 2);
    const float4* sp = (const float4*)slot;
#pragma unroll
    for (int qi = 0; qi < 4; qi++) {
        float4 v = sp[qi * 32 + ls];
        dst[2*qi] = pk2(v.x, v.y); dst[2*qi+1] = pk2(v.z, v.w);
    }
}
__device__ __forceinline__ void f_dots(const u64x2* kvp, const u64x2 qtr[2][8],
                                       float sc[2])
{
#pragma unroll
    for (int hh = 0; hh < 2; hh++) {
        u64x2 d0 = pk2(0.f, 0.f), d1 = pk2(0.f, 0.f);
#pragma unroll
        for (int qi = 0; qi < 4; qi++) {
            d0 = ffma2(qtr[hh][2*qi],   kvp[2*qi],   d0);
            d1 = ffma2(qtr[hh][2*qi+1], kvp[2*qi+1], d1);
        }
        float2 f0 = upk(d0), f1 = upk(d1);
        sc[hh] = f0.x + f0.y + f1.x + f1.y;
    }
}
__device__ __forceinline__ void f_upd(const u64x2* kvp, const float sc[2],
    const float qb[2], float nm, float mh[2], float sh[2], u64x2 acc[2][8])
{
#pragma unroll
    for (int hh = 0; hh < 2; hh++) {
        float s = sc[hh] + qb[hh] + nm;
        if (s <= mh[hh]) {               // warp-uniform (post-reduce)
            float p = __expf(s - mh[hh]);
            sh[hh] += p;
            u64x2 p2 = pk2(p, p);
#pragma unroll
            for (int qi = 0; qi < 8; qi++)
                acc[hh][qi] = ffma2(kvp[qi], p2, acc[hh][qi]);
        } else {
            float c0 = __expf(mh[hh] - s);
            sh[hh] = sh[hh] * c0 + 1.f;
            mh[hh] = s;
            u64x2 c2 = pk2(c0, c0);
#pragma unroll
            for (int qi = 0; qi < 8; qi++)
                acc[hh][qi] = ffma2(acc[hh][qi], c2, kvp[qi]);
        }
    }
}

// grid (N, 4), 8 warps: 4 head-pairs x 2 t-chunks -> 8 segments.
__global__ __launch_bounds__(256) void flash_kernel(
    const float* __restrict__ qt, const float* __restrict__ qs,
    const float* __restrict__ bk, const float* __restrict__ kv,
    const float* __restrict__ extra, const unsigned char* __restrict__ mask,
    float2* __restrict__ fst, float* __restrict__ facc,
    int Tlen, int Tmain, long rs)
{
    extern __shared__ __align__(16) float fsm[];
    int n = blockIdx.x;
    int w = threadIdx.x >> 5, lane = threadIdx.x & 31;
    int hp = w & 3, c = w >> 2, h0 = hp * 2;
    int seg = blockIdx.y * 2 + c;
    int ts = (seg * Tlen) >> 3, te = ((seg + 1) * Tlen) >> 3;

    float* ring = fsm + (size_t)w * (FSLOTS * 512);
    uint32_t ring_s = smem_u32(ring);

    u64x2 qtr[2][8];
#pragma unroll
    for (int hh = 0; hh < 2; hh++) {
        const float4* qp = (const float4*)(qt + ((size_t)n * HH + h0 + hh) * DDIM);
#pragma unroll
        for (int qi = 0; qi < 4; qi++) {
            float4 v = qp[lane + 32 * qi];
            qtr[hh][2*qi] = pk2(v.x, v.y); qtr[hh][2*qi+1] = pk2(v.z, v.w);
        }
    }
    float qb[2];
#pragma unroll
    for (int hh = 0; hh < 2; hh++) {
        int h = h0 + hh;
        float p = qs[(size_t)n * DDIM + h*64 + lane]      * bk[h*64 + lane]
                + qs[(size_t)n * DDIM + h*64 + 32 + lane] * bk[h*64 + 32 + lane];
#pragma unroll
        for (int off = 16; off > 0; off >>= 1)
            p += __shfl_xor_sync(0xffffffffu, p, off);
        qb[hh] = p;
    }
    float mh[2] = {-1e30f, -1e30f}, sh[2] = {0.f, 0.f};
    u64x2 acc[2][8];
#pragma unroll
    for (int hh = 0; hh < 2; hh++)
#pragma unroll
        for (int qi = 0; qi < 8; qi++) acc[hh][qi] = pk2(0.f, 0.f);

    const float* kvn = kv + (size_t)n * DDIM;
    const float* erow = extra + (size_t)n * DDIM;
    const unsigned char* mk = mask ? mask + (size_t)n * Tlen : nullptr;

    auto issue = [&](int t) {
        if (t < te) {
            const float* rowp = (t < Tmain) ? (kvn + (size_t)t * rs) : erow;
            const float* sp = rowp + lane * 16;
            uint32_t base = ring_s + (uint32_t)((t - ts) % FSLOTS) * 2048u;
#pragma unroll
            for (int j = 0; j < 4; j++) {
                uint32_t g = (uint32_t)(lane * 4 + j);
                uint32_t l = g & 31u;
                uint32_t cc = (g & ~31u) | (l ^ (((l >> 3) & 3u) << 2));
                cp16(base + cc * 16u, sp + 4 * j);
            }
        }
        CP_COMMIT();
    };

#pragma unroll
    for (int i = 0; i < FDEPTH; i++) issue(ts + i);

    u64x2 kA[8], kB[8];
    int t = ts;
    while (t < te) {
        bool hasB = (t + 1 < te);
        CP_WAIT(2);
        __syncwarp();
        f_loads(kA, ring + ((t - ts) % FSLOTS) * 512, lane);
        if (hasB) f_loads(kB, ring + ((t + 1 - ts) % FSLOTS) * 512, lane);
        issue(t + FDEPTH);
        issue(t + FDEPTH + 1);
        float sA[2], sB[2] = {0.f, 0.f};
        f_dots(kA, qtr, sA);
        if (hasB) f_dots(kB, qtr, sB);
#pragma unroll
        for (int off = 16; off > 0; off >>= 1) {
            sA[0] += __shfl_xor_sync(0xffffffffu, sA[0], off);
            sA[1] += __shfl_xor_sync(0xffffffffu, sA[1], off);
            sB[0] += __shfl_xor_sync(0xffffffffu, sB[0], off);
            sB[1] += __shfl_xor_sync(0xffffffffu, sB[1], off);
        }
        float nmA = (mk && mk[t]) ? -1e9f : 0.f;
        f_upd(kA, sA, qb, nmA, mh, sh, acc);
        if (hasB) {
            float nmB = (mk && mk[t+1]) ? -1e9f : 0.f;
            f_upd(kB, sB, qb, nmB, mh, sh, acc);
        }
        t += 2;
    }
    CP_WAIT(0);

#pragma unroll
    for (int hh = 0; hh < 2; hh++) {
        size_t base = ((size_t)n * 8 + seg) * HH + h0 + hh;
        if (lane == 0) fst[base] = make_float2(mh[hh], sh[hh]);
        float4* op = (float4*)(facc + base * DDIM);
#pragma unroll
        for (int qi = 0; qi < 4; qi++) {
            float2 a = upk(acc[hh][2*qi]), b = upk(acc[hh][2*qi+1]);
            float4 v = {a.x, a.y, b.x, b.y};
            op[lane + 32 * qi] = v;
        }
    }
}

__global__ __launch_bounds__(256) void merge_kernel(
    const float* __restrict__ facc, const float2* __restrict__ fst,
    float* __restrict__ ctx)
{
    int n = blockIdx.x, w = threadIdx.x >> 5, lane = threadIdx.x & 31;
    float2 st[8]; float M = -1e30f;
#pragma unroll
    for (int s = 0; s < 8; s++) {
        st[s] = fst[((size_t)n * 8 + s) * HH + w];
        M = fmaxf(M, st[s].x);
    }
    float S = 0.f;
#pragma unroll
    for (int s = 0; s < 8; s++) S += st[s].y * __expf(st[s].x - M);
    float inv = 1.f / S;
    float co[8];
#pragma unroll
    for (int s = 0; s < 8; s++) co[s] = __expf(st[s].x - M) * inv;
    float4 out[4];
#pragma unroll
    for (int qi = 0; qi < 4; qi++) out[qi] = make_float4(0.f, 0.f, 0.f, 0.f);
#pragma unroll
    for (int s = 0; s < 8; s++) {
        const float4* ap = (const float4*)(facc + (((size_t)n * 8 + s) * HH + w) * DDIM);
#pragma unroll
        for (int qi = 0; qi < 4; qi++) {
            float4 v = ap[lane + 32 * qi];
            out[qi].x += co[s]*v.x; out[qi].y += co[s]*v.y;
            out[qi].z += co[s]*v.z; out[qi].w += co[s]*v.w;
        }
    }
    float4* op = (float4*)(ctx + ((size_t)n * HH + w) * DDIM);
#pragma unroll
    for (int qi = 0; qi < 4; qi++) op[lane + 32 * qi] = out[qi];
}

// ---------------- host ----------------
static void gemm(const float* A, int lda, int aOffZ,
                 const float* W, int ldw, int wOffZ, bool wt,
                 float* C, int ldc, int cOffZ, long PS, const float* bias,
                 int Kloc, int KS, int Hz, int Mz, float scale, int relu)
{
    dim3 g(4, Mz / 64, Hz * KS);
    if (wt)
        gemm_kernel<true><<<g,256>>>(A,lda,aOffZ,W,ldw,wOffZ,C,ldc,cOffZ,PS,bias,Kloc,KS,scale,relu);
    else
        gemm_kernel<false><<<g,256>>>(A,lda,aOffZ,W,ldw,wOffZ,C,ldc,cOffZ,PS,bias,Kloc,KS,scale,relu);
}
static void red(const float* part, long PS, int KS, const float* bias,
                const float* res, float* C, int M, float scale, int relu)
{
    reduce_kernel<<<(NNH * M) / 512, 128>>>(part, PS, KS, bias, res, C, M, scale, relu);
}

extern "C" void kernel_launch(void* const* d_in, const int* in_sizes, int n_in,
                              void* d_out, int out_size)
{
    (void)in_sizes; (void)n_in; (void)out_size;
    const int*   toks   = (const int*)  d_in[0];
    const float* cached = (const float*)d_in[1];
    const float* memory = (const float*)d_in[2];
    const unsigned char* mmask = (const unsigned char*)d_in[3];
    const float* embd   = (const float*)d_in[4];
    const float* Wqkv_s = (const float*)d_in[5];
    const float* bqkv_s = (const float*)d_in[6];
    const float* Wo_s   = (const float*)d_in[7];
    const float* bo_s   = (const float*)d_in[8];
    const float* Wqkv_c = (const float*)d_in[9];
    const float* bqkv_c = (const float*)d_in[10];
    const float* Wo_c   = (const float*)d_in[11];
    const float* bo_c   = (const float*)d_in[12];
    const float* W1     = (const float*)d_in[13];
    const float* b1     = (const float*)d_in[14];
    const float* W2     = (const float*)d_in[15];
    const float* b2     = (const float*)d_in[16];
    const float* ln1w   = (const float*)d_in[17];
    const float* ln1b   = (const float*)d_in[18];
    const float* ln2w   = (const float*)d_in[19];
    const float* ln2b   = (const float*)d_in[20];
    const float* ln3w   = (const float*)d_in[21];
    const float* ln3b   = (const float*)d_in[22];
    const int*   offp   = (const int*)  d_in[23];
    float* dout = (float*)d_out;

    float *tgt,*q,*o,*qt,*ctx,*part,*facc; float2* fst;
    cudaGetSymbolAddress((void**)&tgt,  g_tgt);
    cudaGetSymbolAddress((void**)&q,    g_q);
    cudaGetSymbolAddress((void**)&o,    g_o);
    cudaGetSymbolAddress((void**)&qt,   g_qt);
    cudaGetSymbolAddress((void**)&ctx,  g_ctx);
    cudaGetSymbolAddress((void**)&part, g_part);
    cudaGetSymbolAddress((void**)&facc, g_facc);
    cudaGetSymbolAddress((void**)&fst,  g_fst);
    float* ff = facc;   // facc region reused for FFN hidden (no overlap in time)

    cudaFuncSetAttribute(flash_kernel,
                         cudaFuncAttributeMaxDynamicSharedMemorySize, FSMEM);

    const long PS_D = (long)NNH * DDIM;
    embed_kernel<<<NNH, 128>>>(toks, embd, offp, tgt);

    for (int l = 0; l < LL; l++) {
        for (int pass = 0; pass < 2; pass++) {
            const float* Wqkv = (pass==0 ? Wqkv_s : Wqkv_c) + (size_t)l*3*DDIM*DDIM;
            const float* bqkv = (pass==0 ? bqkv_s : bqkv_c) + (size_t)l*3*DDIM;
            const float* Wo   = (pass==0 ? Wo_s   : Wo_c)   + (size_t)l*DDIM*DDIM;
            const float* bo   = (pass==0 ? bo_s   : bo_c)   + (size_t)l*DDIM;
            const float* lw   = (pass==0 ? ln1w : ln2w) + (size_t)l*DDIM;
            const float* lb   = (pass==0 ? ln1b : ln2b) + (size_t)l*DDIM;
            const float* kv   = (pass==0) ? cached + (size_t)l*TT*NNH*DDIM : memory;
            int Tlen  = (pass==0) ? TT + 1 : SSL;
            int Tmain = (pass==0) ? TT : SSL;
            const unsigned char* mk = (pass==0) ? nullptr : mmask;

            // q = 0.125*(tgt @ Wq^T + bq), split-K 4
            gemm(tgt, DDIM,0, Wqkv, DDIM,0,false, part, DDIM,0, PS_D, nullptr,
                 DDIM/4,4, 1, DDIM, 1.f,0);
            red(part, PS_D, 4, bqkv, nullptr, q, DDIM, 0.125f, 0);
            // qt[n,h,:] = q[n,h*64:(h+1)*64] @ Wk_h  (WT path, z=head)
            gemm(q, DDIM, DHH, Wqkv + DDIM*DDIM, DDIM, DHH*DDIM, true,
                 qt, HH*DDIM, DDIM, 0, nullptr, DHH,1, HH, DDIM, 1.f,0);
            // flash (swizzled cp.async ring) + merge -> ctx
            flash_kernel<<<dim3(NNH,4),256,FSMEM>>>(qt, q, bqkv + DDIM, kv, tgt, mk,
                                                    fst, facc, Tlen, Tmain, PS_D);
            merge_kernel<<<NNH,256>>>(facc, fst, ctx);
            // o[n, h*64+j] = Wv_h @ ctx[n,h,:] + bv, split-K 4 per head
            gemm(ctx, HH*DDIM, DDIM, Wqkv + 2*DDIM*DDIM, DDIM, DHH*DDIM, false,
                 part, DDIM, DHH, PS_D, nullptr, DDIM/4, 4, HH, DHH, 1.f, 0);
            red(part, PS_D, 4, bqkv + 2*DDIM, nullptr, o, DDIM, 1.f, 0);
            // attn = o @ Wo^T + bo + tgt, split-K 4, fused reduce+residual+LN
            gemm(o, DDIM,0, Wo, DDIM,0,false, part, DDIM,0, PS_D, nullptr,
                 DDIM/4,4, 1, DDIM, 1.f,0);
            ln_red_kernel<<<NNH,128>>>(part, PS_D, 4, bo, tgt, lw, lb, tgt);
        }
        // FFN
        const float* W1l = W1 + (size_t)l*DFF*DDIM;
        const float* W2l = W2 + (size_t)l*DDIM*DFF;
        gemm(tgt, DDIM,0, W1l, DDIM,0,false, part, DFF,0, (long)NNH*DFF, nullptr,
             DDIM/2,2, 1, DFF, 1.f,0);
        red(part, (long)NNH*DFF, 2, b1 + (size_t)l*DFF, nullptr, ff, DFF, 1.f, 1);
        gemm(ff, DFF,0, W2l, DFF,0,false, part, DDIM,0, PS_D, nullptr,
             DFF/8,8, 1, DDIM, 1.f,0);
        ln_red_kernel<<<NNH,128>>>(part, PS_D, 8, b2 + (size_t)l*DDIM, tgt,
                                   ln3w + (size_t)l*DDIM, ln3b + (size_t)l*DDIM,
                                   (l == LL-1) ? dout : tgt);
    }
}